// round 1
// baseline (speedup 1.0000x reference)
#include <cuda_runtime.h>
#include <math.h>

// ---------------- problem constants ----------------
#define BB   4
#define TT   1024
#define DD   512
#define DI   1024
#define NS   16
#define MROWS (BB*TT)      // 4096
#define EPSF 1e-5f

// ---------------- scratch (device globals; no allocs allowed) ----------------
__device__ float g_x   [MROWS*DD];      // running residual stream
__device__ float g_xz  [MROWS*2*DI];    // in_proj output  [x_in | z]
__device__ float g_xc  [MROWS*DI];      // conv+silu output
__device__ float g_dbc [MROWS*64];      // x_proj output [dt_r(32)|B(16)|C(16)]
__device__ float g_dt  [MROWS*DI];      // softplus(dt)
__device__ float g_y   [MROWS*DI];      // scan output (gated)
__device__ float g_tmp [MROWS*DD];      // out_proj output (pre-LN)
__device__ float g_pool[BB*DD];         // pooled vector

// ---------------- block reductions ----------------
__device__ __forceinline__ float block_sum(float v) {
    __shared__ float red[32];
    int lane = threadIdx.x & 31, w = threadIdx.x >> 5;
    int nw = (blockDim.x + 31) >> 5;
    #pragma unroll
    for (int o = 16; o > 0; o >>= 1) v += __shfl_xor_sync(0xffffffffu, v, o);
    if (lane == 0) red[w] = v;
    __syncthreads();
    float s = 0.f;
    for (int i = 0; i < nw; i++) s += red[i];
    __syncthreads();
    return s;
}

__device__ __forceinline__ float block_max(float v) {
    __shared__ float redm[32];
    int lane = threadIdx.x & 31, w = threadIdx.x >> 5;
    int nw = (blockDim.x + 31) >> 5;
    #pragma unroll
    for (int o = 16; o > 0; o >>= 1) v = fmaxf(v, __shfl_xor_sync(0xffffffffu, v, o));
    if (lane == 0) redm[w] = v;
    __syncthreads();
    float m = redm[0];
    for (int i = 1; i < nw; i++) m = fmaxf(m, redm[i]);
    __syncthreads();
    return m;
}

// ---------------- init copy ----------------
__global__ __launch_bounds__(256) void copy_kernel(float* __restrict__ dst,
                                                   const float* __restrict__ src, int n) {
    int i = blockIdx.x * 256 + threadIdx.x;
    if (i < n) dst[i] = src[i];
}

// ---------------- generic fp32 GEMM: C[M,N] = A[M,K] * B[N,K]^T ----------------
// BM=BN=128, BK=16, 256 threads, 8x8 microtile per thread.
#define GBM 128
#define GBN 128
#define GBK 16
#define GPAD 4

__global__ __launch_bounds__(256) void gemm_nt(const float* __restrict__ A,
                                               const float* __restrict__ B,
                                               float* __restrict__ C,
                                               int M, int N, int K) {
    __shared__ __align__(16) float As[GBK][GBM + GPAD];
    __shared__ __align__(16) float Bs[GBK][GBN + GPAD];
    const int bm = blockIdx.x * GBM;
    const int bn = blockIdx.y * GBN;
    const int tid = threadIdx.x;
    const int tx = tid & 15;        // 16 col groups (8 cols each)
    const int ty = tid >> 4;        // 16 row groups (8 rows each)

    float acc[8][8];
    #pragma unroll
    for (int i = 0; i < 8; i++)
        #pragma unroll
        for (int j = 0; j < 8; j++) acc[i][j] = 0.f;

    for (int k0 = 0; k0 < K; k0 += GBK) {
        // load A tile 128x16 (512 float4 slots, 2 per thread)
        #pragma unroll
        for (int s = 0; s < 2; s++) {
            int slot = tid + s * 256;
            int row = slot >> 2;
            int kc = (slot & 3) * 4;
            float4 v = *(const float4*)(A + (size_t)(bm + row) * K + k0 + kc);
            As[kc + 0][row] = v.x; As[kc + 1][row] = v.y;
            As[kc + 2][row] = v.z; As[kc + 3][row] = v.w;
        }
        // load B tile 128x16 with N guard
        #pragma unroll
        for (int s = 0; s < 2; s++) {
            int slot = tid + s * 256;
            int row = slot >> 2;
            int kc = (slot & 3) * 4;
            float4 v = make_float4(0.f, 0.f, 0.f, 0.f);
            if (bn + row < N) v = *(const float4*)(B + (size_t)(bn + row) * K + k0 + kc);
            Bs[kc + 0][row] = v.x; Bs[kc + 1][row] = v.y;
            Bs[kc + 2][row] = v.z; Bs[kc + 3][row] = v.w;
        }
        __syncthreads();

        #pragma unroll
        for (int k = 0; k < GBK; k++) {
            float4 a0 = *(const float4*)&As[k][ty * 8];
            float4 a1 = *(const float4*)&As[k][ty * 8 + 4];
            float4 b0 = *(const float4*)&Bs[k][tx * 8];
            float4 b1 = *(const float4*)&Bs[k][tx * 8 + 4];
            float a[8] = {a0.x, a0.y, a0.z, a0.w, a1.x, a1.y, a1.z, a1.w};
            float bv[8] = {b0.x, b0.y, b0.z, b0.w, b1.x, b1.y, b1.z, b1.w};
            #pragma unroll
            for (int i = 0; i < 8; i++)
                #pragma unroll
                for (int j = 0; j < 8; j++)
                    acc[i][j] = fmaf(a[i], bv[j], acc[i][j]);
        }
        __syncthreads();
    }

    const int col0 = bn + tx * 8;
    #pragma unroll
    for (int i = 0; i < 8; i++) {
        int row = bm + ty * 8 + i;
        if (col0 + 7 < N) {
            float4 v0 = make_float4(acc[i][0], acc[i][1], acc[i][2], acc[i][3]);
            float4 v1 = make_float4(acc[i][4], acc[i][5], acc[i][6], acc[i][7]);
            *(float4*)(C + (size_t)row * N + col0)     = v0;
            *(float4*)(C + (size_t)row * N + col0 + 4) = v1;
        } else {
            #pragma unroll
            for (int j = 0; j < 8; j++)
                if (col0 + j < N) C[(size_t)row * N + col0 + j] = acc[i][j];
        }
    }
}

// ---------------- depthwise causal conv(DC=4) + silu ----------------
__global__ __launch_bounds__(256) void conv_silu(const float* __restrict__ xz,
                                                 float* __restrict__ xc,
                                                 const float* __restrict__ cw,
                                                 const float* __restrict__ cb) {
    int idx = blockIdx.x * 256 + threadIdx.x;
    if (idx >= MROWS * DI) return;
    int d = idx & (DI - 1);
    int m = idx >> 10;           // row index b*T+t
    int t = m & (TT - 1);
    float w0 = cw[d * 4 + 0], w1 = cw[d * 4 + 1], w2 = cw[d * 4 + 2], w3 = cw[d * 4 + 3];
    float acc = cb[d];
    if (t >= 3) acc = fmaf(xz[(size_t)(m - 3) * 2048 + d], w0, acc);
    if (t >= 2) acc = fmaf(xz[(size_t)(m - 2) * 2048 + d], w1, acc);
    if (t >= 1) acc = fmaf(xz[(size_t)(m - 1) * 2048 + d], w2, acc);
    acc = fmaf(xz[(size_t)m * 2048 + d], w3, acc);
    xc[idx] = acc / (1.f + __expf(-acc));   // silu
}

// ---------------- dt = softplus(dt_r @ dt_w^T + dt_b) ----------------
__global__ __launch_bounds__(256) void dt_softplus(const float* __restrict__ dbc,
                                                   float* __restrict__ dt,
                                                   const float* __restrict__ dtw,
                                                   const float* __restrict__ dtb) {
    int idx = blockIdx.x * 256 + threadIdx.x;
    if (idx >= MROWS * DI) return;
    int d = idx & (DI - 1);
    int m = idx >> 10;
    const float4* w  = (const float4*)(dtw + (size_t)d * 32);
    const float4* xr = (const float4*)(dbc + (size_t)m * 64);
    float acc = dtb[d];
    #pragma unroll
    for (int q = 0; q < 8; q++) {
        float4 a = w[q], x = xr[q];
        acc = fmaf(a.x, x.x, acc); acc = fmaf(a.y, x.y, acc);
        acc = fmaf(a.z, x.z, acc); acc = fmaf(a.w, x.w, acc);
    }
    // stable softplus: max(x,0) + log1p(exp(-|x|))
    dt[idx] = fmaxf(acc, 0.f) + log1pf(__expf(-fabsf(acc)));
}

// ---------------- selective scan: one thread per (b,d), 16 states in regs ----------------
__global__ __launch_bounds__(64) void scan_kernel(const float* __restrict__ dt,
                                                  const float* __restrict__ xc,
                                                  const float* __restrict__ xz,
                                                  const float* __restrict__ dbc,
                                                  float* __restrict__ y,
                                                  const float* __restrict__ A_log,
                                                  const float* __restrict__ Dsk_p) {
    int d = blockIdx.x * 64 + threadIdx.x;
    int b = blockIdx.y;
    float A[NS], h[NS];
    #pragma unroll
    for (int n = 0; n < NS; n++) {
        A[n] = -__expf(A_log[(size_t)d * NS + n]);
        h[n] = 0.f;
    }
    float Dsk = Dsk_p[d];
    size_t base = (size_t)b * TT;
    const float*  dtp = dt  + base * DI + d;
    const float*  xcp = xc  + base * DI + d;
    const float*  zp  = xz  + base * 2048 + DI + d;
    const float4* bcp = (const float4*)(dbc + base * 64);
    float* yp = y + base * DI + d;

    for (int t = 0; t < TT; t++) {
        float dtv = dtp[(size_t)t * DI];
        float xcv = xcp[(size_t)t * DI];
        float u = dtv * xcv;
        const float4* r = bcp + t * 16 + 8;   // B at float offset 32
        float Bv[16], Cv[16];
        float4 q;
        q = r[0]; Bv[0]=q.x; Bv[1]=q.y; Bv[2]=q.z; Bv[3]=q.w;
        q = r[1]; Bv[4]=q.x; Bv[5]=q.y; Bv[6]=q.z; Bv[7]=q.w;
        q = r[2]; Bv[8]=q.x; Bv[9]=q.y; Bv[10]=q.z; Bv[11]=q.w;
        q = r[3]; Bv[12]=q.x; Bv[13]=q.y; Bv[14]=q.z; Bv[15]=q.w;
        q = r[4]; Cv[0]=q.x; Cv[1]=q.y; Cv[2]=q.z; Cv[3]=q.w;
        q = r[5]; Cv[4]=q.x; Cv[5]=q.y; Cv[6]=q.z; Cv[7]=q.w;
        q = r[6]; Cv[8]=q.x; Cv[9]=q.y; Cv[10]=q.z; Cv[11]=q.w;
        q = r[7]; Cv[12]=q.x; Cv[13]=q.y; Cv[14]=q.z; Cv[15]=q.w;

        float acc = 0.f;
        #pragma unroll
        for (int n = 0; n < NS; n++) {
            float dA = __expf(dtv * A[n]);
            h[n] = fmaf(dA, h[n], u * Bv[n]);
            acc = fmaf(h[n], Cv[n], acc);
        }
        float zv = zp[(size_t)t * 2048];
        float sil = zv / (1.f + __expf(-zv));
        yp[(size_t)t * DI] = (acc + xcv * Dsk) * sil;
    }
}

// ---------------- layernorm(out_proj) + residual, in-place into g_x ----------------
__global__ __launch_bounds__(128) void ln_residual(const float* __restrict__ tmp,
                                                   float* __restrict__ x,
                                                   const float* __restrict__ gg,
                                                   const float* __restrict__ bb) {
    int m = blockIdx.x;
    int tid = threadIdx.x;
    const float* row = tmp + (size_t)m * DD;
    float v[4], s = 0.f, s2 = 0.f;
    #pragma unroll
    for (int i = 0; i < 4; i++) {
        v[i] = row[tid + i * 128];
        s += v[i]; s2 = fmaf(v[i], v[i], s2);
    }
    s  = block_sum(s);
    s2 = block_sum(s2);
    float mu = s * (1.f / DD);
    float var = s2 * (1.f / DD) - mu * mu;
    float rs = rsqrtf(var + EPSF);
    #pragma unroll
    for (int i = 0; i < 4; i++) {
        int c = tid + i * 128;
        size_t idx = (size_t)m * DD + c;
        x[idx] = (v[i] - mu) * rs * gg[c] + bb[c] + x[idx];
    }
}

// ---------------- attention pooling over T ----------------
__global__ __launch_bounds__(256) void pool_kernel(const float* __restrict__ x,
                                                   const float* __restrict__ aw,
                                                   const float* __restrict__ ab,
                                                   float* __restrict__ pooled) {
    __shared__ float sc[TT];
    int b = blockIdx.x, tid = threadIdx.x;
    const float* xb = x + (size_t)b * TT * DD;
    const float4* wr = (const float4*)aw;
    for (int t = tid; t < TT; t += 256) {
        const float4* xr = (const float4*)(xb + (size_t)t * DD);
        float s = 0.f;
        #pragma unroll 4
        for (int q = 0; q < DD / 4; q++) {
            float4 xv = xr[q], wv = wr[q];
            s = fmaf(xv.x, wv.x, s); s = fmaf(xv.y, wv.y, s);
            s = fmaf(xv.z, wv.z, s); s = fmaf(xv.w, wv.w, s);
        }
        sc[t] = s + ab[0];
    }
    __syncthreads();
    float mx = -1e30f;
    for (int t = tid; t < TT; t += 256) mx = fmaxf(mx, sc[t]);
    mx = block_max(mx);
    float sum = 0.f;
    for (int t = tid; t < TT; t += 256) {
        float e = __expf(sc[t] - mx);
        sc[t] = e;
        sum += e;
    }
    sum = block_sum(sum);
    float inv = 1.f / sum;
    for (int dcol = tid; dcol < DD; dcol += 256) {
        float acc = 0.f;
        for (int t = 0; t < TT; t++)
            acc = fmaf(sc[t], xb[(size_t)t * DD + dcol], acc);
        pooled[b * DD + dcol] = acc * inv;
    }
}

// ---------------- MLP head ----------------
__device__ __forceinline__ float gelu_exact(float x) {
    return 0.5f * x * (1.f + erff(x * 0.70710678118654752f));
}

__global__ __launch_bounds__(128) void head_kernel(const float* __restrict__ pooled,
        const float* __restrict__ h1w, const float* __restrict__ h1b,
        const float* __restrict__ g1,  const float* __restrict__ b1,
        const float* __restrict__ h2w, const float* __restrict__ h2b,
        const float* __restrict__ g2,  const float* __restrict__ b2,
        const float* __restrict__ h3w, const float* __restrict__ h3b,
        float* __restrict__ out) {
    int b = blockIdx.x, j = threadIdx.x;   // 128 threads
    __shared__ float sh[128];
    const float4* pr = (const float4*)(pooled + (size_t)b * DD);
    const float4* wr = (const float4*)(h1w + (size_t)j * DD);
    float acc = h1b[j];
    #pragma unroll 4
    for (int q = 0; q < DD / 4; q++) {
        float4 p = pr[q], w = wr[q];
        acc = fmaf(p.x, w.x, acc); acc = fmaf(p.y, w.y, acc);
        acc = fmaf(p.z, w.z, acc); acc = fmaf(p.w, w.w, acc);
    }
    float s  = block_sum(acc);
    float s2 = block_sum(acc * acc);
    float mu = s * (1.f / 128.f);
    float var = s2 * (1.f / 128.f) - mu * mu;
    float x1 = (acc - mu) * rsqrtf(var + EPSF) * g1[j] + b1[j];
    x1 = gelu_exact(x1);
    sh[j] = x1;
    __syncthreads();
    float acc2 = h2b[j];
    #pragma unroll 4
    for (int k = 0; k < 128; k++)
        acc2 = fmaf(sh[k], h2w[(size_t)j * 128 + k], acc2);
    s  = block_sum(acc2);
    s2 = block_sum(acc2 * acc2);
    mu = s * (1.f / 128.f);
    var = s2 * (1.f / 128.f) - mu * mu;
    float x2 = (acc2 - mu) * rsqrtf(var + EPSF) * g2[j] + b2[j];
    x2 = gelu_exact(x2);
    float c = block_sum(x2 * h3w[j]);
    if (j == 0) out[b] = c + h3b[0];
}

// ---------------- launch ----------------
extern "C" void kernel_launch(void* const* d_in, const int* in_sizes, int n_in,
                              void* d_out, int out_size) {
    static float *px = nullptr, *pxz, *pxc, *pdbc, *pdt, *py, *ptmp, *ppool;
    if (!px) {
        cudaGetSymbolAddress((void**)&px,    g_x);
        cudaGetSymbolAddress((void**)&pxz,   g_xz);
        cudaGetSymbolAddress((void**)&pxc,   g_xc);
        cudaGetSymbolAddress((void**)&pdbc,  g_dbc);
        cudaGetSymbolAddress((void**)&pdt,   g_dt);
        cudaGetSymbolAddress((void**)&py,    g_y);
        cudaGetSymbolAddress((void**)&ptmp,  g_tmp);
        cudaGetSymbolAddress((void**)&ppool, g_pool);
    }
    const float* ds     = (const float*)d_in[0];
    const float* in_w   = (const float*)d_in[1];
    const float* conv_w = (const float*)d_in[2];
    const float* conv_b = (const float*)d_in[3];
    const float* xp_w   = (const float*)d_in[4];
    const float* dt_w   = (const float*)d_in[5];
    const float* dt_b   = (const float*)d_in[6];
    const float* A_log  = (const float*)d_in[7];
    const float* D_skip = (const float*)d_in[8];
    const float* out_w  = (const float*)d_in[9];
    const float* ln_g   = (const float*)d_in[10];
    const float* ln_b   = (const float*)d_in[11];
    const float* attn_w = (const float*)d_in[12];
    const float* attn_b = (const float*)d_in[13];
    const float* h1w    = (const float*)d_in[14];
    const float* h1b    = (const float*)d_in[15];
    const float* g1     = (const float*)d_in[16];
    const float* b1     = (const float*)d_in[17];
    const float* h2w    = (const float*)d_in[18];
    const float* h2b    = (const float*)d_in[19];
    const float* g2     = (const float*)d_in[20];
    const float* b2     = (const float*)d_in[21];
    const float* h3w    = (const float*)d_in[22];
    const float* h3b    = (const float*)d_in[23];
    float* out = (float*)d_out;

    copy_kernel<<<(MROWS * DD) / 256, 256>>>(px, ds, MROWS * DD);

    for (int l = 0; l < 4; l++) {
        const float* inwl  = in_w   + (size_t)l * 2048 * 512;
        const float* cwl   = conv_w + (size_t)l * DI * 4;
        const float* cbl   = conv_b + (size_t)l * DI;
        const float* xpwl  = xp_w   + (size_t)l * 64 * DI;
        const float* dtwl  = dt_w   + (size_t)l * DI * 32;
        const float* dtbl  = dt_b   + (size_t)l * DI;
        const float* alogl = A_log  + (size_t)l * DI * NS;
        const float* dskl  = D_skip + (size_t)l * DI;
        const float* outwl = out_w  + (size_t)l * DD * DI;
        const float* lngl  = ln_g   + (size_t)l * DD;
        const float* lnbl  = ln_b   + (size_t)l * DD;

        gemm_nt<<<dim3(MROWS / GBM, 2048 / GBN), 256>>>(px, inwl, pxz, MROWS, 2048, 512);
        conv_silu<<<(MROWS * DI) / 256, 256>>>(pxz, pxc, cwl, cbl);
        gemm_nt<<<dim3(MROWS / GBM, 1), 256>>>(pxc, xpwl, pdbc, MROWS, 64, 1024);
        dt_softplus<<<(MROWS * DI) / 256, 256>>>(pdbc, pdt, dtwl, dtbl);
        scan_kernel<<<dim3(DI / 64, BB), 64>>>(pdt, pxc, pxz, pdbc, py, alogl, dskl);
        gemm_nt<<<dim3(MROWS / GBM, DD / GBN), 256>>>(py, outwl, ptmp, MROWS, 512, 1024);
        ln_residual<<<MROWS, 128>>>(ptmp, px, lngl, lnbl);
    }

    pool_kernel<<<BB, 256>>>(px, attn_w, attn_b, ppool);
    head_kernel<<<BB, 128>>>(ppool, h1w, h1b, g1, b1, h2w, h2b, g2, b2, h3w, h3b, out);
}